// round 1
// baseline (speedup 1.0000x reference)
#include <cuda_runtime.h>
#include <math.h>

#define D_MODEL 1024
#define N_RES   2048
#define BATCH   32
#define TWO_D   2048

// ---- scratch (device globals; no allocation allowed) ----
__device__ __align__(16) float g_xcombT[TWO_D * BATCH];     // [k][b] transposed concat(x_real,x_imag)
__device__ __align__(16) float g_xcT  [D_MODEL * BATCH];    // [d][b] transposed x_collapsed
__device__ __align__(16) float g_rw   [N_RES * D_MODEL];    // 1/(1+|W|)
__device__ __align__(16) float g_cosT [N_RES * BATCH];      // [n][b]
__device__ __align__(16) float g_sinT [N_RES * BATCH];      // [n][b]

// ---------------------------------------------------------------------------
// K0: precompute reciprocal wavelength + transpose inputs
// ---------------------------------------------------------------------------
__global__ void prep_kernel(const float* __restrict__ xr,
                            const float* __restrict__ xi,
                            const float* __restrict__ W) {
    int i = blockIdx.x * blockDim.x + threadIdx.x;
    int stride = gridDim.x * blockDim.x;
    for (int idx = i; idx < N_RES * D_MODEL; idx += stride) {
        float w = W[idx];
        g_rw[idx] = 1.0f / (1.0f + fabsf(w));   // precise divide (prep is mem-bound anyway)
    }
    for (int idx = i; idx < TWO_D * BATCH; idx += stride) {
        int k = idx >> 5;          // / BATCH
        int b = idx & 31;          // % BATCH
        float v = (k < D_MODEL) ? xr[b * D_MODEL + k]
                                : xi[b * D_MODEL + (k - D_MODEL)];
        g_xcombT[idx] = v;
    }
}

// ---------------------------------------------------------------------------
// K1: input projection  x_collapsed[b,d] = sum_k xcomb[b,k]*ipw[d,k] + ipb[d]
// warp per d, lane per b; weight loads are warp-uniform float4
// ---------------------------------------------------------------------------
__global__ void proj_kernel(const float* __restrict__ ipw,
                            const float* __restrict__ ipb) {
    int warp = (blockIdx.x * blockDim.x + threadIdx.x) >> 5;
    int lane = threadIdx.x & 31;
    if (warp >= D_MODEL) return;
    const float* wrow = ipw + (size_t)warp * TWO_D;
    float a0 = 0.f, a1 = 0.f, a2 = 0.f, a3 = 0.f;
    #pragma unroll 4
    for (int k = 0; k < TWO_D; k += 4) {
        float4 w4 = *(const float4*)(wrow + k);
        a0 = fmaf(g_xcombT[(k + 0) * BATCH + lane], w4.x, a0);
        a1 = fmaf(g_xcombT[(k + 1) * BATCH + lane], w4.y, a1);
        a2 = fmaf(g_xcombT[(k + 2) * BATCH + lane], w4.z, a2);
        a3 = fmaf(g_xcombT[(k + 3) * BATCH + lane], w4.w, a3);
    }
    g_xcT[warp * BATCH + lane] = ((a0 + a1) + (a2 + a3)) + __ldg(ipb + warp);
}

// ---------------------------------------------------------------------------
// K2: resonance. warp per n, lane per batch b.
// theta = xc[b,d]*rw[n,d] + B[n,d] + t[b];  accumulate sin/cos over d.
// MUFU-bound: 2 MUFU per (n,d) warp-iteration.
// ---------------------------------------------------------------------------
__global__ void __launch_bounds__(128)
resonance_kernel(const float* __restrict__ Bmat,
                 const float* __restrict__ t) {
    int warp = (blockIdx.x * blockDim.x + threadIdx.x) >> 5;
    int lane = threadIdx.x & 31;
    if (warp >= N_RES) return;

    const float tl = __ldg(t + lane);
    const float* rwrow = g_rw + (size_t)warp * D_MODEL;
    const float* brow  = Bmat + (size_t)warp * D_MODEL;

    float ca = 0.f, sa = 0.f;
    #pragma unroll 2
    for (int d = 0; d < D_MODEL; d += 4) {
        float4 rw4 = *(const float4*)(rwrow + d);
        float4 b4  = *(const float4*)(brow  + d);

        float xc0 = g_xcT[(d + 0) * BATCH + lane];
        float xc1 = g_xcT[(d + 1) * BATCH + lane];
        float xc2 = g_xcT[(d + 2) * BATCH + lane];
        float xc3 = g_xcT[(d + 3) * BATCH + lane];

        float th0 = fmaf(xc0, rw4.x, b4.x + tl);
        float th1 = fmaf(xc1, rw4.y, b4.y + tl);
        float th2 = fmaf(xc2, rw4.z, b4.z + tl);
        float th3 = fmaf(xc3, rw4.w, b4.w + tl);

        sa += __sinf(th0);  ca += __cosf(th0);
        sa += __sinf(th1);  ca += __cosf(th1);
        sa += __sinf(th2);  ca += __cosf(th2);
        sa += __sinf(th3);  ca += __cosf(th3);
    }
    g_cosT[warp * BATCH + lane] = ca;
    g_sinT[warp * BATCH + lane] = sa;
}

// ---------------------------------------------------------------------------
// K3: output projection + silu.
// warp per output row (first 1024 rows: real, next 1024: imag), lane per b.
// out[b,d] = silu( sum_n sumT[n][b] * w[d,n] )
// ---------------------------------------------------------------------------
__global__ void outproj_kernel(const float* __restrict__ wr,
                               const float* __restrict__ wi,
                               float* __restrict__ out) {
    int warp = (blockIdx.x * blockDim.x + threadIdx.x) >> 5;
    int lane = threadIdx.x & 31;
    if (warp >= 2 * D_MODEL) return;

    const bool  is_imag = (warp >= D_MODEL);
    const int   d       = is_imag ? (warp - D_MODEL) : warp;
    const float* wrow   = (is_imag ? wi : wr) + (size_t)d * N_RES;
    const float* src    = is_imag ? g_sinT : g_cosT;

    float a0 = 0.f, a1 = 0.f, a2 = 0.f, a3 = 0.f;
    #pragma unroll 4
    for (int n = 0; n < N_RES; n += 4) {
        float4 w4 = *(const float4*)(wrow + n);
        a0 = fmaf(src[(n + 0) * BATCH + lane], w4.x, a0);
        a1 = fmaf(src[(n + 1) * BATCH + lane], w4.y, a1);
        a2 = fmaf(src[(n + 2) * BATCH + lane], w4.z, a2);
        a3 = fmaf(src[(n + 3) * BATCH + lane], w4.w, a3);
    }
    float x = (a0 + a1) + (a2 + a3);
    float y = x / (1.0f + expf(-x));      // silu
    out[(is_imag ? BATCH * D_MODEL : 0) + lane * D_MODEL + d] = y;
}

// ---------------------------------------------------------------------------
extern "C" void kernel_launch(void* const* d_in, const int* in_sizes, int n_in,
                              void* d_out, int out_size) {
    const float* x_real = (const float*)d_in[0];
    const float* x_imag = (const float*)d_in[1];
    const float* t      = (const float*)d_in[2];
    const float* ipw    = (const float*)d_in[3];
    const float* ipb    = (const float*)d_in[4];
    const float* W      = (const float*)d_in[5];
    const float* Bmat   = (const float*)d_in[6];
    const float* orw    = (const float*)d_in[7];
    const float* oiw    = (const float*)d_in[8];
    float* out = (float*)d_out;

    prep_kernel<<<2048, 256>>>(x_real, x_imag, W);
    proj_kernel<<<(D_MODEL * 32 + 127) / 128, 128>>>(ipw, ipb);
    resonance_kernel<<<(N_RES * 32 + 127) / 128, 128>>>(Bmat, t);
    outproj_kernel<<<(2 * D_MODEL * 32 + 127) / 128, 128>>>(orw, oiw, out);
}

// round 2
// speedup vs baseline: 1.4695x; 1.4695x over previous
#include <cuda_runtime.h>
#include <math.h>

#define D_MODEL 1024
#define N_RES   2048
#define BATCH   32
#define TWO_D   2048
#define TILE_D  8

// ---- scratch (device globals; no allocation allowed) ----
__device__ __align__(16) float g_xcombT[TWO_D * BATCH];     // [k][b]
__device__ __align__(16) float g_xcT  [D_MODEL * BATCH];    // [d][b]
__device__ __align__(16) float g_rw   [N_RES * D_MODEL];    // 1/(1+|W|)
__device__ __align__(16) float g_cosT [N_RES * BATCH];      // [n][b]
__device__ __align__(16) float g_sinT [N_RES * BATCH];      // [n][b]

// ---------------------------------------------------------------------------
// K0: precompute reciprocal wavelength (float4 stream) + transpose inputs
// ---------------------------------------------------------------------------
__global__ void prep_kernel(const float* __restrict__ xr,
                            const float* __restrict__ xi,
                            const float* __restrict__ W) {
    int i = blockIdx.x * blockDim.x + threadIdx.x;
    int stride = gridDim.x * blockDim.x;

    const float4* W4 = (const float4*)W;
    float4* rw4 = (float4*)g_rw;
    const int n4 = N_RES * D_MODEL / 4;
    for (int idx = i; idx < n4; idx += stride) {
        float4 w = W4[idx];
        float4 r;
        r.x = 1.0f / (1.0f + fabsf(w.x));
        r.y = 1.0f / (1.0f + fabsf(w.y));
        r.z = 1.0f / (1.0f + fabsf(w.z));
        r.w = 1.0f / (1.0f + fabsf(w.w));
        rw4[idx] = r;
    }
    for (int idx = i; idx < TWO_D * BATCH; idx += stride) {
        int k = idx >> 5;          // / BATCH
        int b = idx & 31;          // % BATCH
        float v = (k < D_MODEL) ? xr[b * D_MODEL + k]
                                : xi[b * D_MODEL + (k - D_MODEL)];
        g_xcombT[idx] = v;
    }
}

// ---------------------------------------------------------------------------
// K1: input projection, tiled.
// block = 8 output rows d; 8 warps split k-range; lane = batch b.
// ---------------------------------------------------------------------------
__global__ void __launch_bounds__(256)
proj_kernel(const float* __restrict__ ipw,
            const float* __restrict__ ipb) {
    __shared__ float red[8][TILE_D][32];
    const int dt   = blockIdx.x * TILE_D;          // 128 blocks
    const int w    = threadIdx.x >> 5;
    const int lane = threadIdx.x & 31;

    float acc[TILE_D];
    #pragma unroll
    for (int i = 0; i < TILE_D; i++) acc[i] = 0.f;

    const int kchunk = TWO_D / 8;                  // 256
    const int k0 = w * kchunk;
    for (int k = k0; k < k0 + kchunk; k += 4) {
        float s0 = g_xcombT[(k + 0) * BATCH + lane];
        float s1 = g_xcombT[(k + 1) * BATCH + lane];
        float s2 = g_xcombT[(k + 2) * BATCH + lane];
        float s3 = g_xcombT[(k + 3) * BATCH + lane];
        #pragma unroll
        for (int i = 0; i < TILE_D; i++) {
            float4 w4 = *(const float4*)(ipw + (size_t)(dt + i) * TWO_D + k);
            acc[i] = fmaf(s3, w4.w, fmaf(s2, w4.z, fmaf(s1, w4.y, fmaf(s0, w4.x, acc[i]))));
        }
    }
    #pragma unroll
    for (int i = 0; i < TILE_D; i++) red[w][i][lane] = acc[i];
    __syncthreads();

    const int td = threadIdx.x >> 5;               // 0..7
    float s = 0.f;
    #pragma unroll
    for (int ww = 0; ww < 8; ww++) s += red[ww][td][lane];
    const int d = dt + td;
    g_xcT[d * BATCH + lane] = s + __ldg(ipb + d);
}

// ---------------------------------------------------------------------------
// K2: resonance. warp per n, lane per batch b. MUFU-bound.
// ---------------------------------------------------------------------------
__global__ void __launch_bounds__(128)
resonance_kernel(const float* __restrict__ Bmat,
                 const float* __restrict__ t) {
    int warp = (blockIdx.x * blockDim.x + threadIdx.x) >> 5;
    int lane = threadIdx.x & 31;
    if (warp >= N_RES) return;

    const float tl = __ldg(t + lane);
    const float* rwrow = g_rw + (size_t)warp * D_MODEL;
    const float* brow  = Bmat + (size_t)warp * D_MODEL;

    float ca = 0.f, sa = 0.f;
    #pragma unroll 2
    for (int d = 0; d < D_MODEL; d += 4) {
        float4 rw4 = *(const float4*)(rwrow + d);
        float4 b4  = *(const float4*)(brow  + d);

        float xc0 = g_xcT[(d + 0) * BATCH + lane];
        float xc1 = g_xcT[(d + 1) * BATCH + lane];
        float xc2 = g_xcT[(d + 2) * BATCH + lane];
        float xc3 = g_xcT[(d + 3) * BATCH + lane];

        float th0 = fmaf(xc0, rw4.x, b4.x + tl);
        float th1 = fmaf(xc1, rw4.y, b4.y + tl);
        float th2 = fmaf(xc2, rw4.z, b4.z + tl);
        float th3 = fmaf(xc3, rw4.w, b4.w + tl);

        sa += __sinf(th0);  ca += __cosf(th0);
        sa += __sinf(th1);  ca += __cosf(th1);
        sa += __sinf(th2);  ca += __cosf(th2);
        sa += __sinf(th3);  ca += __cosf(th3);
    }
    g_cosT[warp * BATCH + lane] = ca;
    g_sinT[warp * BATCH + lane] = sa;
}

// ---------------------------------------------------------------------------
// K3: output projection + silu, tiled like K1.
// block = (side, 8 output rows); 8 warps split n; lane = b.
// ---------------------------------------------------------------------------
__global__ void __launch_bounds__(256)
outproj_kernel(const float* __restrict__ wr,
               const float* __restrict__ wi,
               float* __restrict__ out) {
    __shared__ float red[8][TILE_D][32];
    const int nblk_side = D_MODEL / TILE_D;        // 128
    const bool is_imag  = blockIdx.x >= nblk_side;
    const int  dt       = (is_imag ? blockIdx.x - nblk_side : blockIdx.x) * TILE_D;
    const int  w        = threadIdx.x >> 5;
    const int  lane     = threadIdx.x & 31;

    const float* wbase = is_imag ? wi : wr;
    const float* src   = is_imag ? g_sinT : g_cosT;

    float acc[TILE_D];
    #pragma unroll
    for (int i = 0; i < TILE_D; i++) acc[i] = 0.f;

    const int nchunk = N_RES / 8;                  // 256
    const int n0 = w * nchunk;
    for (int n = n0; n < n0 + nchunk; n += 4) {
        float s0 = src[(n + 0) * BATCH + lane];
        float s1 = src[(n + 1) * BATCH + lane];
        float s2 = src[(n + 2) * BATCH + lane];
        float s3 = src[(n + 3) * BATCH + lane];
        #pragma unroll
        for (int i = 0; i < TILE_D; i++) {
            float4 w4 = *(const float4*)(wbase + (size_t)(dt + i) * N_RES + n);
            acc[i] = fmaf(s3, w4.w, fmaf(s2, w4.z, fmaf(s1, w4.y, fmaf(s0, w4.x, acc[i]))));
        }
    }
    #pragma unroll
    for (int i = 0; i < TILE_D; i++) red[w][i][lane] = acc[i];
    __syncthreads();

    const int td = threadIdx.x >> 5;
    float s = 0.f;
    #pragma unroll
    for (int ww = 0; ww < 8; ww++) s += red[ww][td][lane];
    float y = s / (1.0f + __expf(-s));             // silu
    const int d = dt + td;
    out[(is_imag ? BATCH * D_MODEL : 0) + lane * D_MODEL + d] = y;
}

// ---------------------------------------------------------------------------
extern "C" void kernel_launch(void* const* d_in, const int* in_sizes, int n_in,
                              void* d_out, int out_size) {
    const float* x_real = (const float*)d_in[0];
    const float* x_imag = (const float*)d_in[1];
    const float* t      = (const float*)d_in[2];
    const float* ipw    = (const float*)d_in[3];
    const float* ipb    = (const float*)d_in[4];
    const float* W      = (const float*)d_in[5];
    const float* Bmat   = (const float*)d_in[6];
    const float* orw    = (const float*)d_in[7];
    const float* oiw    = (const float*)d_in[8];
    float* out = (float*)d_out;

    prep_kernel<<<512, 256>>>(x_real, x_imag, W);
    proj_kernel<<<D_MODEL / TILE_D, 256>>>(ipw, ipb);
    resonance_kernel<<<(N_RES * 32) / 128, 128>>>(Bmat, t);
    outproj_kernel<<<2 * (D_MODEL / TILE_D), 256>>>(orw, oiw, out);
}

// round 3
// speedup vs baseline: 2.4002x; 1.6333x over previous
#include <cuda_runtime.h>
#include <math.h>

#define D_MODEL 1024
#define N_RES   2048
#define BATCH   32
#define TWO_D   2048
#define TILE_D  8
#define KSPLIT  4
#define NSPLIT  4

// ---- scratch (device globals; no allocation allowed) ----
__device__ __align__(16) float g_xcombT[TWO_D * BATCH];                 // [k][b]
__device__ __align__(16) float g_xc_part[KSPLIT * D_MODEL * BATCH];    // [s][d][b]
__device__ __align__(16) float g_xcT  [D_MODEL * BATCH];               // [d][b]
__device__ __align__(16) float g_rw   [N_RES * D_MODEL];               // 1/(1+|W|)
__device__ __align__(16) float g_cosT [N_RES * BATCH];                 // [n][b]
__device__ __align__(16) float g_sinT [N_RES * BATCH];                 // [n][b]
__device__ __align__(16) float g_out_part[NSPLIT * 2 * D_MODEL * BATCH]; // [s][row][b]

// ---------------------------------------------------------------------------
// K0: reciprocal wavelength (float4 stream) + transpose inputs
// ---------------------------------------------------------------------------
__global__ void prep_kernel(const float* __restrict__ xr,
                            const float* __restrict__ xi,
                            const float* __restrict__ W) {
    int i = blockIdx.x * blockDim.x + threadIdx.x;
    int stride = gridDim.x * blockDim.x;

    const float4* W4 = (const float4*)W;
    float4* rw4 = (float4*)g_rw;
    const int n4 = N_RES * D_MODEL / 4;
    for (int idx = i; idx < n4; idx += stride) {
        float4 w = W4[idx];
        float4 r;
        r.x = 1.0f / (1.0f + fabsf(w.x));
        r.y = 1.0f / (1.0f + fabsf(w.y));
        r.z = 1.0f / (1.0f + fabsf(w.z));
        r.w = 1.0f / (1.0f + fabsf(w.w));
        rw4[idx] = r;
    }
    for (int idx = i; idx < TWO_D * BATCH; idx += stride) {
        int k = idx >> 5;
        int b = idx & 31;
        float v = (k < D_MODEL) ? xr[b * D_MODEL + k]
                                : xi[b * D_MODEL + (k - D_MODEL)];
        g_xcombT[idx] = v;
    }
}

// ---------------------------------------------------------------------------
// K1: input projection, split-K partials.
// grid (128 dtiles, KSPLIT). block 256: 8 warps split this block's k-range.
// ---------------------------------------------------------------------------
__global__ void __launch_bounds__(256)
proj_kernel(const float* __restrict__ ipw) {
    __shared__ float red[8][TILE_D][32];
    const int dt    = blockIdx.x * TILE_D;
    const int split = blockIdx.y;
    const int w     = threadIdx.x >> 5;
    const int lane  = threadIdx.x & 31;

    float acc[TILE_D];
    #pragma unroll
    for (int i = 0; i < TILE_D; i++) acc[i] = 0.f;

    const int kblk   = TWO_D / KSPLIT;          // 512
    const int kchunk = kblk / 8;                // 64
    const int k0 = split * kblk + w * kchunk;
    for (int k = k0; k < k0 + kchunk; k += 4) {
        float s0 = g_xcombT[(k + 0) * BATCH + lane];
        float s1 = g_xcombT[(k + 1) * BATCH + lane];
        float s2 = g_xcombT[(k + 2) * BATCH + lane];
        float s3 = g_xcombT[(k + 3) * BATCH + lane];
        #pragma unroll
        for (int i = 0; i < TILE_D; i++) {
            float4 w4 = *(const float4*)(ipw + (size_t)(dt + i) * TWO_D + k);
            acc[i] = fmaf(s3, w4.w, fmaf(s2, w4.z, fmaf(s1, w4.y, fmaf(s0, w4.x, acc[i]))));
        }
    }
    #pragma unroll
    for (int i = 0; i < TILE_D; i++) red[w][i][lane] = acc[i];
    __syncthreads();

    const int td = threadIdx.x >> 5;
    float s = 0.f;
    #pragma unroll
    for (int ww = 0; ww < 8; ww++) s += red[ww][td][lane];
    g_xc_part[(split * D_MODEL + dt + td) * BATCH + lane] = s;
}

// K1b: combine split-K partials + bias -> g_xcT[d][b]
__global__ void combine_xc_kernel(const float* __restrict__ ipb) {
    int idx = blockIdx.x * blockDim.x + threadIdx.x;   // D*B threads
    if (idx >= D_MODEL * BATCH) return;
    int d = idx >> 5;
    float s = 0.f;
    #pragma unroll
    for (int sp = 0; sp < KSPLIT; sp++)
        s += g_xc_part[sp * D_MODEL * BATCH + idx];
    g_xcT[idx] = s + __ldg(ipb + d);
}

// ---------------------------------------------------------------------------
// K2: resonance with coalesced smem staging.
// block = 8 warps; warp w owns n = n0+w, lane = batch b.
// Stage rw/B in 128-d chunks (coalesced), compute from LDS broadcast.
// ---------------------------------------------------------------------------
#define CHUNK 128
__global__ void __launch_bounds__(256)
resonance_kernel(const float* __restrict__ Bmat,
                 const float* __restrict__ t) {
    __shared__ float s_rw[8 * CHUNK];
    __shared__ float s_B [8 * CHUNK];

    const int n0   = blockIdx.x * 8;
    const int w    = threadIdx.x >> 5;
    const int lane = threadIdx.x & 31;
    const float tl = __ldg(t + lane);

    float ca0 = 0.f, ca1 = 0.f, sa0 = 0.f, sa1 = 0.f;

    for (int c0 = 0; c0 < D_MODEL; c0 += CHUNK) {
        // cooperative coalesced stage: thread -> one float4 per array
        {
            const int r   = threadIdx.x >> 5;        // row 0..7
            const int off = (threadIdx.x & 31) * 4;  // 0..124
            *(float4*)(s_rw + r * CHUNK + off) =
                *(const float4*)(g_rw + (size_t)(n0 + r) * D_MODEL + c0 + off);
            *(float4*)(s_B + r * CHUNK + off) =
                *(const float4*)(Bmat + (size_t)(n0 + r) * D_MODEL + c0 + off);
        }
        __syncthreads();

        #pragma unroll 4
        for (int d = 0; d < CHUNK; d += 4) {
            float4 rw4 = *(const float4*)(s_rw + w * CHUNK + d);
            float4 b4  = *(const float4*)(s_B  + w * CHUNK + d);

            int gd = c0 + d;
            float xc0 = g_xcT[(gd + 0) * BATCH + lane];
            float xc1 = g_xcT[(gd + 1) * BATCH + lane];
            float xc2 = g_xcT[(gd + 2) * BATCH + lane];
            float xc3 = g_xcT[(gd + 3) * BATCH + lane];

            float th0 = fmaf(xc0, rw4.x, b4.x + tl);
            float th1 = fmaf(xc1, rw4.y, b4.y + tl);
            float th2 = fmaf(xc2, rw4.z, b4.z + tl);
            float th3 = fmaf(xc3, rw4.w, b4.w + tl);

            sa0 += __sinf(th0);  ca0 += __cosf(th0);
            sa1 += __sinf(th1);  ca1 += __cosf(th1);
            sa0 += __sinf(th2);  ca0 += __cosf(th2);
            sa1 += __sinf(th3);  ca1 += __cosf(th3);
        }
        __syncthreads();
    }
    g_cosT[(n0 + w) * BATCH + lane] = ca0 + ca1;
    g_sinT[(n0 + w) * BATCH + lane] = sa0 + sa1;
}

// ---------------------------------------------------------------------------
// K3: output projection, split-N partials.
// grid (128 dtiles, NSPLIT, 2 sides). block 256.
// ---------------------------------------------------------------------------
__global__ void __launch_bounds__(256)
outproj_kernel(const float* __restrict__ wr,
               const float* __restrict__ wi) {
    __shared__ float red[8][TILE_D][32];
    const int  dt      = blockIdx.x * TILE_D;
    const int  split   = blockIdx.y;
    const bool is_imag = blockIdx.z != 0;
    const int  w       = threadIdx.x >> 5;
    const int  lane    = threadIdx.x & 31;

    const float* wbase = is_imag ? wi : wr;
    const float* src   = is_imag ? g_sinT : g_cosT;

    float acc[TILE_D];
    #pragma unroll
    for (int i = 0; i < TILE_D; i++) acc[i] = 0.f;

    const int nblk   = N_RES / NSPLIT;          // 512
    const int nchunk = nblk / 8;                // 64
    const int n0 = split * nblk + w * nchunk;
    for (int n = n0; n < n0 + nchunk; n += 4) {
        float s0 = src[(n + 0) * BATCH + lane];
        float s1 = src[(n + 1) * BATCH + lane];
        float s2 = src[(n + 2) * BATCH + lane];
        float s3 = src[(n + 3) * BATCH + lane];
        #pragma unroll
        for (int i = 0; i < TILE_D; i++) {
            float4 w4 = *(const float4*)(wbase + (size_t)(dt + i) * N_RES + n);
            acc[i] = fmaf(s3, w4.w, fmaf(s2, w4.z, fmaf(s1, w4.y, fmaf(s0, w4.x, acc[i]))));
        }
    }
    #pragma unroll
    for (int i = 0; i < TILE_D; i++) red[w][i][lane] = acc[i];
    __syncthreads();

    const int td = threadIdx.x >> 5;
    float s = 0.f;
    #pragma unroll
    for (int ww = 0; ww < 8; ww++) s += red[ww][td][lane];
    const int row = (is_imag ? D_MODEL : 0) + dt + td;
    g_out_part[(split * 2 * D_MODEL + row) * BATCH + lane] = s;
}

// K3b: combine split-N partials, silu, transpose-store
__global__ void combine_out_kernel(float* __restrict__ out) {
    int idx = blockIdx.x * blockDim.x + threadIdx.x;   // 2*D*B threads
    if (idx >= 2 * D_MODEL * BATCH) return;
    int row = idx >> 5;
    int b   = idx & 31;
    float s = 0.f;
    #pragma unroll
    for (int sp = 0; sp < NSPLIT; sp++)
        s += g_out_part[sp * 2 * D_MODEL * BATCH + idx];
    float y = s / (1.0f + __expf(-s));
    int is_imag = row >= D_MODEL;
    int d = row & (D_MODEL - 1);
    out[(is_imag ? BATCH * D_MODEL : 0) + b * D_MODEL + d] = y;
}

// ---------------------------------------------------------------------------
extern "C" void kernel_launch(void* const* d_in, const int* in_sizes, int n_in,
                              void* d_out, int out_size) {
    const float* x_real = (const float*)d_in[0];
    const float* x_imag = (const float*)d_in[1];
    const float* t      = (const float*)d_in[2];
    const float* ipw    = (const float*)d_in[3];
    const float* ipb    = (const float*)d_in[4];
    const float* W      = (const float*)d_in[5];
    const float* Bmat   = (const float*)d_in[6];
    const float* orw    = (const float*)d_in[7];
    const float* oiw    = (const float*)d_in[8];
    float* out = (float*)d_out;

    prep_kernel<<<512, 256>>>(x_real, x_imag, W);
    proj_kernel<<<dim3(D_MODEL / TILE_D, KSPLIT), 256>>>(ipw);
    combine_xc_kernel<<<(D_MODEL * BATCH + 255) / 256, 256>>>(ipb);
    resonance_kernel<<<N_RES / 8, 256>>>(Bmat, t);
    outproj_kernel<<<dim3(D_MODEL / TILE_D, NSPLIT, 2), 256>>>(orw, oiw);
    combine_out_kernel<<<(2 * D_MODEL * BATCH + 255) / 256, 256>>>(out);
}

// round 4
// speedup vs baseline: 2.7757x; 1.1565x over previous
#include <cuda_runtime.h>
#include <math.h>

#define D_MODEL 1024
#define N_RES   2048
#define BATCH   32
#define TWO_D   2048
#define TILE_D  8
#define KSPLIT  4
#define NSPLIT  4
#define DSPLIT  4

// ---- scratch (device globals; no allocation allowed) ----
__device__ __align__(16) float g_xcombT[TWO_D * BATCH];                  // [k][b]
__device__ __align__(16) float g_xc_part[KSPLIT * D_MODEL * BATCH];      // [s][d][b]
__device__ __align__(16) float g_xcT  [D_MODEL * BATCH];                 // [d][b]
__device__ __align__(16) float g_rw   [N_RES * D_MODEL];                 // 1/(1+|W|)
__device__ __align__(16) float g_cos_part[DSPLIT * N_RES * BATCH];       // [s][n][b]
__device__ __align__(16) float g_sin_part[DSPLIT * N_RES * BATCH];
__device__ __align__(16) float g_cosT [N_RES * BATCH];                   // rotated sums [n][b]
__device__ __align__(16) float g_sinT [N_RES * BATCH];
__device__ __align__(16) float g_out_part[NSPLIT * 2 * D_MODEL * BATCH]; // [s][row][b]

// ---------------------------------------------------------------------------
// K0: reciprocal wavelength (float4 stream) + transpose inputs
// ---------------------------------------------------------------------------
__global__ void prep_kernel(const float* __restrict__ xr,
                            const float* __restrict__ xi,
                            const float* __restrict__ W) {
    int i = blockIdx.x * blockDim.x + threadIdx.x;
    int stride = gridDim.x * blockDim.x;

    const float4* W4 = (const float4*)W;
    float4* rw4 = (float4*)g_rw;
    const int n4 = N_RES * D_MODEL / 4;
    for (int idx = i; idx < n4; idx += stride) {
        float4 w = W4[idx];
        float4 r;
        r.x = 1.0f / (1.0f + fabsf(w.x));
        r.y = 1.0f / (1.0f + fabsf(w.y));
        r.z = 1.0f / (1.0f + fabsf(w.z));
        r.w = 1.0f / (1.0f + fabsf(w.w));
        rw4[idx] = r;
    }
    for (int idx = i; idx < TWO_D * BATCH; idx += stride) {
        int k = idx >> 5;
        int b = idx & 31;
        float v = (k < D_MODEL) ? xr[b * D_MODEL + k]
                                : xi[b * D_MODEL + (k - D_MODEL)];
        g_xcombT[idx] = v;
    }
}

// ---------------------------------------------------------------------------
// K1: input projection, split-K partials.
// ---------------------------------------------------------------------------
__global__ void __launch_bounds__(256)
proj_kernel(const float* __restrict__ ipw) {
    __shared__ float red[8][TILE_D][32];
    const int dt    = blockIdx.x * TILE_D;
    const int split = blockIdx.y;
    const int w     = threadIdx.x >> 5;
    const int lane  = threadIdx.x & 31;

    float acc[TILE_D];
    #pragma unroll
    for (int i = 0; i < TILE_D; i++) acc[i] = 0.f;

    const int kblk   = TWO_D / KSPLIT;          // 512
    const int kchunk = kblk / 8;                // 64
    const int k0 = split * kblk + w * kchunk;
    for (int k = k0; k < k0 + kchunk; k += 4) {
        float s0 = g_xcombT[(k + 0) * BATCH + lane];
        float s1 = g_xcombT[(k + 1) * BATCH + lane];
        float s2 = g_xcombT[(k + 2) * BATCH + lane];
        float s3 = g_xcombT[(k + 3) * BATCH + lane];
        #pragma unroll
        for (int i = 0; i < TILE_D; i++) {
            float4 w4 = *(const float4*)(ipw + (size_t)(dt + i) * TWO_D + k);
            acc[i] = fmaf(s3, w4.w, fmaf(s2, w4.z, fmaf(s1, w4.y, fmaf(s0, w4.x, acc[i]))));
        }
    }
    #pragma unroll
    for (int i = 0; i < TILE_D; i++) red[w][i][lane] = acc[i];
    __syncthreads();

    const int td = threadIdx.x >> 5;
    float s = 0.f;
    #pragma unroll
    for (int ww = 0; ww < 8; ww++) s += red[ww][td][lane];
    g_xc_part[(split * D_MODEL + dt + td) * BATCH + lane] = s;
}

// K1b: combine split-K partials + bias
__global__ void combine_xc_kernel(const float* __restrict__ ipb) {
    int idx = blockIdx.x * blockDim.x + threadIdx.x;
    if (idx >= D_MODEL * BATCH) return;
    int d = idx >> 5;
    float s = 0.f;
    #pragma unroll
    for (int sp = 0; sp < KSPLIT; sp++)
        s += g_xc_part[sp * D_MODEL * BATCH + idx];
    g_xcT[idx] = s + __ldg(ipb + d);
}

// ---------------------------------------------------------------------------
// K2: resonance, d-split, t hoisted out (rotation applied in combine).
// grid (N/8, DSPLIT); block 256: warp w owns n = n0+w, lane = batch b.
// core = xc*rw + B;  accumulate sin(core), cos(core).
// ---------------------------------------------------------------------------
#define CHUNK 128
__global__ void __launch_bounds__(256)
resonance_kernel(const float* __restrict__ Bmat) {
    __shared__ float s_rw[8 * CHUNK];
    __shared__ float s_B [8 * CHUNK];

    const int n0    = blockIdx.x * 8;
    const int split = blockIdx.y;
    const int d0    = split * (D_MODEL / DSPLIT);   // 256-wide d range
    const int w     = threadIdx.x >> 5;
    const int lane  = threadIdx.x & 31;

    float ca0 = 0.f, ca1 = 0.f, sa0 = 0.f, sa1 = 0.f;

    for (int c0 = d0; c0 < d0 + D_MODEL / DSPLIT; c0 += CHUNK) {
        {
            const int r   = threadIdx.x >> 5;
            const int off = (threadIdx.x & 31) * 4;
            *(float4*)(s_rw + r * CHUNK + off) =
                *(const float4*)(g_rw + (size_t)(n0 + r) * D_MODEL + c0 + off);
            *(float4*)(s_B + r * CHUNK + off) =
                *(const float4*)(Bmat + (size_t)(n0 + r) * D_MODEL + c0 + off);
        }
        __syncthreads();

        #pragma unroll 4
        for (int d = 0; d < CHUNK; d += 4) {
            float4 rw4 = *(const float4*)(s_rw + w * CHUNK + d);
            float4 b4  = *(const float4*)(s_B  + w * CHUNK + d);

            int gd = c0 + d;
            float xc0 = g_xcT[(gd + 0) * BATCH + lane];
            float xc1 = g_xcT[(gd + 1) * BATCH + lane];
            float xc2 = g_xcT[(gd + 2) * BATCH + lane];
            float xc3 = g_xcT[(gd + 3) * BATCH + lane];

            float th0 = fmaf(xc0, rw4.x, b4.x);
            float th1 = fmaf(xc1, rw4.y, b4.y);
            float th2 = fmaf(xc2, rw4.z, b4.z);
            float th3 = fmaf(xc3, rw4.w, b4.w);

            sa0 += __sinf(th0);  ca0 += __cosf(th0);
            sa1 += __sinf(th1);  ca1 += __cosf(th1);
            sa0 += __sinf(th2);  ca0 += __cosf(th2);
            sa1 += __sinf(th3);  ca1 += __cosf(th3);
        }
        __syncthreads();
    }
    g_cos_part[(split * N_RES + n0 + w) * BATCH + lane] = ca0 + ca1;
    g_sin_part[(split * N_RES + n0 + w) * BATCH + lane] = sa0 + sa1;
}

// K2b: combine d-split partials and rotate by t[b]:
//   cos_sum = C*cos t - S*sin t ; sin_sum = S*cos t + C*sin t
__global__ void combine_res_kernel(const float* __restrict__ t) {
    int idx = blockIdx.x * blockDim.x + threadIdx.x;   // N*B
    if (idx >= N_RES * BATCH) return;
    int b = idx & 31;
    float C = 0.f, S = 0.f;
    #pragma unroll
    for (int sp = 0; sp < DSPLIT; sp++) {
        C += g_cos_part[sp * N_RES * BATCH + idx];
        S += g_sin_part[sp * N_RES * BATCH + idx];
    }
    float st, ct;
    __sincosf(__ldg(t + b), &st, &ct);
    g_cosT[idx] = fmaf(C, ct, -S * st);
    g_sinT[idx] = fmaf(S, ct,  C * st);
}

// ---------------------------------------------------------------------------
// K3: output projection, split-N partials.
// ---------------------------------------------------------------------------
__global__ void __launch_bounds__(256)
outproj_kernel(const float* __restrict__ wr,
               const float* __restrict__ wi) {
    __shared__ float red[8][TILE_D][32];
    const int  dt      = blockIdx.x * TILE_D;
    const int  split   = blockIdx.y;
    const bool is_imag = blockIdx.z != 0;
    const int  w       = threadIdx.x >> 5;
    const int  lane    = threadIdx.x & 31;

    const float* wbase = is_imag ? wi : wr;
    const float* src   = is_imag ? g_sinT : g_cosT;

    float acc[TILE_D];
    #pragma unroll
    for (int i = 0; i < TILE_D; i++) acc[i] = 0.f;

    const int nblk   = N_RES / NSPLIT;          // 512
    const int nchunk = nblk / 8;                // 64
    const int n0 = split * nblk + w * nchunk;
    for (int n = n0; n < n0 + nchunk; n += 4) {
        float s0 = src[(n + 0) * BATCH + lane];
        float s1 = src[(n + 1) * BATCH + lane];
        float s2 = src[(n + 2) * BATCH + lane];
        float s3 = src[(n + 3) * BATCH + lane];
        #pragma unroll
        for (int i = 0; i < TILE_D; i++) {
            float4 w4 = *(const float4*)(wbase + (size_t)(dt + i) * N_RES + n);
            acc[i] = fmaf(s3, w4.w, fmaf(s2, w4.z, fmaf(s1, w4.y, fmaf(s0, w4.x, acc[i]))));
        }
    }
    #pragma unroll
    for (int i = 0; i < TILE_D; i++) red[w][i][lane] = acc[i];
    __syncthreads();

    const int td = threadIdx.x >> 5;
    float s = 0.f;
    #pragma unroll
    for (int ww = 0; ww < 8; ww++) s += red[ww][td][lane];
    const int row = (is_imag ? D_MODEL : 0) + dt + td;
    g_out_part[(split * 2 * D_MODEL + row) * BATCH + lane] = s;
}

// K3b: combine split-N partials, silu, transpose-store
__global__ void combine_out_kernel(float* __restrict__ out) {
    int idx = blockIdx.x * blockDim.x + threadIdx.x;
    if (idx >= 2 * D_MODEL * BATCH) return;
    int row = idx >> 5;
    int b   = idx & 31;
    float s = 0.f;
    #pragma unroll
    for (int sp = 0; sp < NSPLIT; sp++)
        s += g_out_part[sp * 2 * D_MODEL * BATCH + idx];
    float y = s / (1.0f + __expf(-s));
    int is_imag = row >= D_MODEL;
    int d = row & (D_MODEL - 1);
    out[(is_imag ? BATCH * D_MODEL : 0) + b * D_MODEL + d] = y;
}

// ---------------------------------------------------------------------------
extern "C" void kernel_launch(void* const* d_in, const int* in_sizes, int n_in,
                              void* d_out, int out_size) {
    const float* x_real = (const float*)d_in[0];
    const float* x_imag = (const float*)d_in[1];
    const float* t      = (const float*)d_in[2];
    const float* ipw    = (const float*)d_in[3];
    const float* ipb    = (const float*)d_in[4];
    const float* W      = (const float*)d_in[5];
    const float* Bmat   = (const float*)d_in[6];
    const float* orw    = (const float*)d_in[7];
    const float* oiw    = (const float*)d_in[8];
    float* out = (float*)d_out;

    prep_kernel<<<1024, 256>>>(x_real, x_imag, W);
    proj_kernel<<<dim3(D_MODEL / TILE_D, KSPLIT), 256>>>(ipw);
    combine_xc_kernel<<<(D_MODEL * BATCH + 255) / 256, 256>>>(ipb);
    resonance_kernel<<<dim3(N_RES / 8, DSPLIT), 256>>>(Bmat);
    combine_res_kernel<<<(N_RES * BATCH + 255) / 256, 256>>>(t);
    outproj_kernel<<<dim3(D_MODEL / TILE_D, NSPLIT, 2), 256>>>(orw, oiw);
    combine_out_kernel<<<(2 * D_MODEL * BATCH + 255) / 256, 256>>>(out);
}

// round 5
// speedup vs baseline: 3.2937x; 1.1866x over previous
#include <cuda_runtime.h>
#include <math.h>

#define D_MODEL 1024
#define N_RES   2048
#define BATCH   32
#define TWO_D   2048
#define TILE_D  8
#define KSPLIT  4
#define NSPLIT  4
#define DSPLIT  8
#define CHUNK   128

// ---- scratch (device globals; no allocation allowed) ----
__device__ __align__(16) float g_xcombT[TWO_D * BATCH];                  // [k][b]
__device__ __align__(16) float g_xc_part[KSPLIT * D_MODEL * BATCH];      // [s][d][b]
__device__ __align__(16) float g_xcT  [D_MODEL * BATCH];                 // [d][b]
__device__ __align__(16) float g_rw   [N_RES * D_MODEL];                 // 1/(1+|W|)
__device__ __align__(16) float g_cos_part[DSPLIT * N_RES * BATCH];       // [s][n][b]
__device__ __align__(16) float g_sin_part[DSPLIT * N_RES * BATCH];
__device__ __align__(16) float g_cosT [N_RES * BATCH];                   // rotated sums [n][b]
__device__ __align__(16) float g_sinT [N_RES * BATCH];
__device__ __align__(16) float g_out_part[NSPLIT * 2 * D_MODEL * BATCH]; // [s][row][b]

// ---------------------------------------------------------------------------
// K0: reciprocal wavelength (float4 stream) + transpose inputs
// ---------------------------------------------------------------------------
__global__ void prep_kernel(const float* __restrict__ xr,
                            const float* __restrict__ xi,
                            const float* __restrict__ W) {
    int i = blockIdx.x * blockDim.x + threadIdx.x;
    int stride = gridDim.x * blockDim.x;

    const float4* W4 = (const float4*)W;
    float4* rw4 = (float4*)g_rw;
    const int n4 = N_RES * D_MODEL / 4;
    for (int idx = i; idx < n4; idx += stride) {
        float4 w = W4[idx];
        float4 r;
        r.x = 1.0f / (1.0f + fabsf(w.x));
        r.y = 1.0f / (1.0f + fabsf(w.y));
        r.z = 1.0f / (1.0f + fabsf(w.z));
        r.w = 1.0f / (1.0f + fabsf(w.w));
        rw4[idx] = r;
    }
    for (int idx = i; idx < TWO_D * BATCH; idx += stride) {
        int k = idx >> 5;
        int b = idx & 31;
        float v = (k < D_MODEL) ? xr[b * D_MODEL + k]
                                : xi[b * D_MODEL + (k - D_MODEL)];
        g_xcombT[idx] = v;
    }
}

// ---------------------------------------------------------------------------
// K1: input projection, split-K, weights staged in smem (coalesced).
// block = 8 rows x 512-k tile; 8 warps split the 512 k; lane = b.
// ---------------------------------------------------------------------------
__global__ void __launch_bounds__(256)
proj_kernel(const float* __restrict__ ipw) {
    __shared__ float s_w[TILE_D * 512];          // 16 KB
    __shared__ float red[8][TILE_D][32];         // 8 KB
    const int dt    = blockIdx.x * TILE_D;
    const int split = blockIdx.y;
    const int kbase = split * 512;
    const int w     = threadIdx.x >> 5;
    const int lane  = threadIdx.x & 31;

    // coalesced stage: 1024 float4s by 256 threads
    #pragma unroll
    for (int p = 0; p < 4; p++) {
        int idx = p * 256 + threadIdx.x;         // float4 index
        int r = idx >> 7;                        // row 0..7
        int c = (idx & 127) * 4;                 // col 0..508
        *(float4*)(s_w + r * 512 + c) =
            *(const float4*)(ipw + (size_t)(dt + r) * TWO_D + kbase + c);
    }
    __syncthreads();

    float acc[TILE_D];
    #pragma unroll
    for (int i = 0; i < TILE_D; i++) acc[i] = 0.f;

    const int k0 = w * 64;                       // warp's k-chunk in tile
    for (int k = k0; k < k0 + 64; k += 4) {
        int gk = kbase + k;
        float s0 = g_xcombT[(gk + 0) * BATCH + lane];
        float s1 = g_xcombT[(gk + 1) * BATCH + lane];
        float s2 = g_xcombT[(gk + 2) * BATCH + lane];
        float s3 = g_xcombT[(gk + 3) * BATCH + lane];
        #pragma unroll
        for (int i = 0; i < TILE_D; i++) {
            float4 w4 = *(const float4*)(s_w + i * 512 + k);
            acc[i] = fmaf(s3, w4.w, fmaf(s2, w4.z, fmaf(s1, w4.y, fmaf(s0, w4.x, acc[i]))));
        }
    }
    #pragma unroll
    for (int i = 0; i < TILE_D; i++) red[w][i][lane] = acc[i];
    __syncthreads();

    const int td = threadIdx.x >> 5;
    float s = 0.f;
    #pragma unroll
    for (int ww = 0; ww < 8; ww++) s += red[ww][td][lane];
    g_xc_part[(split * D_MODEL + dt + td) * BATCH + lane] = s;
}

// K1b: combine split-K partials + bias
__global__ void combine_xc_kernel(const float* __restrict__ ipb) {
    int idx = blockIdx.x * blockDim.x + threadIdx.x;
    if (idx >= D_MODEL * BATCH) return;
    int d = idx >> 5;
    float s = 0.f;
    #pragma unroll
    for (int sp = 0; sp < KSPLIT; sp++)
        s += g_xc_part[sp * D_MODEL * BATCH + idx];
    g_xcT[idx] = s + __ldg(ipb + d);
}

// ---------------------------------------------------------------------------
// K2: resonance, 8-way d-split; one 128-d chunk per block.
// warp w owns n = n0+w, lane = b.  core = xc*rw + B (t applied in combine).
// ---------------------------------------------------------------------------
__global__ void __launch_bounds__(256, 6)
resonance_kernel(const float* __restrict__ Bmat) {
    __shared__ float s_rw[8 * CHUNK];
    __shared__ float s_B [8 * CHUNK];

    const int n0    = blockIdx.x * 8;
    const int split = blockIdx.y;
    const int c0    = split * CHUNK;
    const int w     = threadIdx.x >> 5;
    const int lane  = threadIdx.x & 31;

    {
        const int r   = threadIdx.x >> 5;
        const int off = (threadIdx.x & 31) * 4;
        *(float4*)(s_rw + r * CHUNK + off) =
            *(const float4*)(g_rw + (size_t)(n0 + r) * D_MODEL + c0 + off);
        *(float4*)(s_B + r * CHUNK + off) =
            *(const float4*)(Bmat + (size_t)(n0 + r) * D_MODEL + c0 + off);
    }
    __syncthreads();

    float ca0 = 0.f, ca1 = 0.f, sa0 = 0.f, sa1 = 0.f;

    #pragma unroll 4
    for (int d = 0; d < CHUNK; d += 4) {
        float4 rw4 = *(const float4*)(s_rw + w * CHUNK + d);
        float4 b4  = *(const float4*)(s_B  + w * CHUNK + d);

        int gd = c0 + d;
        float xc0 = g_xcT[(gd + 0) * BATCH + lane];
        float xc1 = g_xcT[(gd + 1) * BATCH + lane];
        float xc2 = g_xcT[(gd + 2) * BATCH + lane];
        float xc3 = g_xcT[(gd + 3) * BATCH + lane];

        float th0 = fmaf(xc0, rw4.x, b4.x);
        float th1 = fmaf(xc1, rw4.y, b4.y);
        float th2 = fmaf(xc2, rw4.z, b4.z);
        float th3 = fmaf(xc3, rw4.w, b4.w);

        sa0 += __sinf(th0);  ca0 += __cosf(th0);
        sa1 += __sinf(th1);  ca1 += __cosf(th1);
        sa0 += __sinf(th2);  ca0 += __cosf(th2);
        sa1 += __sinf(th3);  ca1 += __cosf(th3);
    }
    g_cos_part[(split * N_RES + n0 + w) * BATCH + lane] = ca0 + ca1;
    g_sin_part[(split * N_RES + n0 + w) * BATCH + lane] = sa0 + sa1;
}

// K2b: combine d-split partials and rotate by t[b]
__global__ void combine_res_kernel(const float* __restrict__ t) {
    int idx = blockIdx.x * blockDim.x + threadIdx.x;   // N*B
    if (idx >= N_RES * BATCH) return;
    int b = idx & 31;
    float C = 0.f, S = 0.f;
    #pragma unroll
    for (int sp = 0; sp < DSPLIT; sp++) {
        C += g_cos_part[sp * N_RES * BATCH + idx];
        S += g_sin_part[sp * N_RES * BATCH + idx];
    }
    float st, ct;
    __sincosf(__ldg(t + b), &st, &ct);
    g_cosT[idx] = fmaf(C, ct, -S * st);
    g_sinT[idx] = fmaf(S, ct,  C * st);
}

// ---------------------------------------------------------------------------
// K3: output projection, split-N, weights staged in smem (coalesced).
// ---------------------------------------------------------------------------
__global__ void __launch_bounds__(256)
outproj_kernel(const float* __restrict__ wr,
               const float* __restrict__ wi) {
    __shared__ float s_w[TILE_D * 512];          // 16 KB
    __shared__ float red[8][TILE_D][32];
    const int  dt      = blockIdx.x * TILE_D;
    const int  split   = blockIdx.y;
    const bool is_imag = blockIdx.z != 0;
    const int  nbase   = split * 512;
    const int  w       = threadIdx.x >> 5;
    const int  lane    = threadIdx.x & 31;

    const float* wbase = is_imag ? wi : wr;
    const float* src   = is_imag ? g_sinT : g_cosT;

    #pragma unroll
    for (int p = 0; p < 4; p++) {
        int idx = p * 256 + threadIdx.x;
        int r = idx >> 7;
        int c = (idx & 127) * 4;
        *(float4*)(s_w + r * 512 + c) =
            *(const float4*)(wbase + (size_t)(dt + r) * N_RES + nbase + c);
    }
    __syncthreads();

    float acc[TILE_D];
    #pragma unroll
    for (int i = 0; i < TILE_D; i++) acc[i] = 0.f;

    const int n0 = w * 64;
    for (int n = n0; n < n0 + 64; n += 4) {
        int gn = nbase + n;
        float s0 = src[(gn + 0) * BATCH + lane];
        float s1 = src[(gn + 1) * BATCH + lane];
        float s2 = src[(gn + 2) * BATCH + lane];
        float s3 = src[(gn + 3) * BATCH + lane];
        #pragma unroll
        for (int i = 0; i < TILE_D; i++) {
            float4 w4 = *(const float4*)(s_w + i * 512 + n);
            acc[i] = fmaf(s3, w4.w, fmaf(s2, w4.z, fmaf(s1, w4.y, fmaf(s0, w4.x, acc[i]))));
        }
    }
    #pragma unroll
    for (int i = 0; i < TILE_D; i++) red[w][i][lane] = acc[i];
    __syncthreads();

    const int td = threadIdx.x >> 5;
    float s = 0.f;
    #pragma unroll
    for (int ww = 0; ww < 8; ww++) s += red[ww][td][lane];
    const int row = (is_imag ? D_MODEL : 0) + dt + td;
    g_out_part[(split * 2 * D_MODEL + row) * BATCH + lane] = s;
}

// K3b: combine split-N partials, silu, transpose-store
__global__ void combine_out_kernel(float* __restrict__ out) {
    int idx = blockIdx.x * blockDim.x + threadIdx.x;
    if (idx >= 2 * D_MODEL * BATCH) return;
    int row = idx >> 5;
    int b   = idx & 31;
    float s = 0.f;
    #pragma unroll
    for (int sp = 0; sp < NSPLIT; sp++)
        s += g_out_part[sp * 2 * D_MODEL * BATCH + idx];
    float y = s / (1.0f + __expf(-s));
    int is_imag = row >= D_MODEL;
    int d = row & (D_MODEL - 1);
    out[(is_imag ? BATCH * D_MODEL : 0) + b * D_MODEL + d] = y;
}

// ---------------------------------------------------------------------------
extern "C" void kernel_launch(void* const* d_in, const int* in_sizes, int n_in,
                              void* d_out, int out_size) {
    const float* x_real = (const float*)d_in[0];
    const float* x_imag = (const float*)d_in[1];
    const float* t      = (const float*)d_in[2];
    const float* ipw    = (const float*)d_in[3];
    const float* ipb    = (const float*)d_in[4];
    const float* W      = (const float*)d_in[5];
    const float* Bmat   = (const float*)d_in[6];
    const float* orw    = (const float*)d_in[7];
    const float* oiw    = (const float*)d_in[8];
    float* out = (float*)d_out;

    prep_kernel<<<1024, 256>>>(x_real, x_imag, W);
    proj_kernel<<<dim3(D_MODEL / TILE_D, KSPLIT), 256>>>(ipw);
    combine_xc_kernel<<<(D_MODEL * BATCH + 255) / 256, 256>>>(ipb);
    resonance_kernel<<<dim3(N_RES / 8, DSPLIT), 256>>>(Bmat);
    combine_res_kernel<<<(N_RES * BATCH + 255) / 256, 256>>>(t);
    outproj_kernel<<<dim3(D_MODEL / TILE_D, NSPLIT, 2), 256>>>(orw, oiw);
    combine_out_kernel<<<(2 * D_MODEL * BATCH + 255) / 256, 256>>>(out);
}